// round 8
// baseline (speedup 1.0000x reference)
#include <cuda_runtime.h>

// Problem constants (fixed by the dataset's setup_inputs)
#define BB 1024
#define TT 512
#define CC 64
#define TAG_START 62
#define TAG_STOP  63

typedef unsigned long long ull;

// Scratch (no device allocation allowed -> __device__ globals)
__device__ float gRes[BB];           // per-batch (logZ - gold)
__device__ unsigned int gTicket = 0; // self-resetting completion ticket (wraps mod BB)

// ---------------------------------------------------------------------------
// Packed f32x2 helpers (sm_100+)
// ---------------------------------------------------------------------------
__device__ __forceinline__ ull ffma2(ull a, ull b, ull c) {
    ull d;
    asm("fma.rn.f32x2 %0, %1, %2, %3;" : "=l"(d) : "l"(a), "l"(b), "l"(c));
    return d;
}
__device__ __forceinline__ ull fadd2(ull a, ull b) {
    ull d;
    asm("add.rn.f32x2 %0, %1, %2;" : "=l"(d) : "l"(a), "l"(b));
    return d;
}
__device__ __forceinline__ float2 upk2(ull a) {
    float2 f;
    asm("mov.b64 {%0, %1}, %2;" : "=f"(f.x), "=f"(f.y) : "l"(a));
    return f;
}
__device__ __forceinline__ ull pk2(float x, float y) {
    ull d;
    asm("mov.b64 %0, {%1, %2};" : "=l"(d) : "f"(x), "f"(y));
    return d;
}

// ---------------------------------------------------------------------------
// Fused CRF kernel: TWO WARPS (64 threads) per batch element.
// Thread j owns output tag column j (one column -> no register spills:
// E column = 32 ull = 64 regs; prior 2-col design hit the 255-reg cap and
// spilled, showing up as 43% L1 traffic).
//   state: p[j] = exp(alpha[j] - M) in shared, M = running log-scale.
//   step:  q[j] = sum_i p[i]*E[i][j] (packed f32x2 over i, 32 ffma2/thread),
//          p_new[j] = q[j] * exp(emit[t][j])
//   renorm every 8 steps (8*10.3 < 88.7 fp32 overflow margin).
// Emissions front-batched 8-deep in registers (MLP=8 hides 577cyc DRAM);
// warp w loads a contiguous 128B row-half per step -> fully coalesced.
// Gold path fused. Tags arrive int32 (JAX x64-off coercion).
// Last finishing block (atomicInc ticket) does the deterministic mean.
// ---------------------------------------------------------------------------
__global__ __launch_bounds__(64) void crf_fused_kernel(
    const float* __restrict__ emissions,      // (B, T, C) f32
    const float* __restrict__ trans,          // (C, C)    f32
    const int* __restrict__ tags,             // (B, T)    i32
    const int* __restrict__ mask,             // (B, T)    i32
    float* __restrict__ out)                  // scalar
{
    __shared__ __align__(16) float p[2][CC];
    __shared__ float red[2];
    __shared__ unsigned char tagS[TT];
    __shared__ unsigned char maskS[TT];

    const int j = threadIdx.x;   // 0..63 = owned column
    const int b = blockIdx.x;
    const int w = j >> 5;        // warp id (0,1)
    const int lane = j & 31;

    const float* eb = emissions + (size_t)b * TT * CC;

    // Stage tags/mask for this sequence into shared (u8)
    for (int k = j; k < TT; k += 64) {
        tagS[k]  = (unsigned char)tags[(size_t)b * TT + k];
        maskS[k] = (unsigned char)(mask[(size_t)b * TT + k] != 0);
    }

    // E column j packed across i: EC[m] = (exp(trans[2m][j]), exp(trans[2m+1][j])).
    // expf(-10000) underflows to 0 == forbidden transition. trans is L2-hot.
    ull EC[CC / 2];
#pragma unroll
    for (int m = 0; m < CC / 2; m++) {
        float v0 = trans[(size_t)(2 * m) * CC + j];
        float v1 = trans[(size_t)(2 * m + 1) * CC + j];
        EC[m] = pk2(expf(v0), expf(v1));
    }

    // init p
    float cur = (j == TAG_START) ? 1.0f : 0.0f;
    p[0][j] = cur;

    float M = 0.0f;          // log-scale (identical in all threads)
    float gold = 0.0f;       // this thread's gold-score contributions
    int prev = TAG_START;    // previous tag (identical in all threads)

    // Emission buffers: 8 steps per bank, front-batched loads (MLP=8).
    float ebufA[8], ebufB[8];
#pragma unroll
    for (int s = 0; s < 8; s++)
        ebufA[s] = eb[(size_t)s * CC + j];

    __syncthreads();

#define STEP8(CUR, NXT, TBASE)                                              \
    {                                                                       \
        const int tbase = (TBASE);                                          \
        if (tbase + 8 < TT) {                                               \
            _Pragma("unroll")                                               \
            for (int s = 0; s < 8; s++)                                     \
                NXT[s] = eb[(size_t)(tbase + 8 + s) * CC + j];              \
        }                                                                   \
        _Pragma("unroll")                                                   \
        for (int s = 0; s < 8; s++) {                                       \
            const int t = tbase + s;                                        \
            const int tg = tagS[t];                                         \
            const int m  = maskS[t];                                        \
            const ulonglong2* pv = (const ulonglong2*)&p[s & 1][0];         \
            ull a0 = 0ull, a1 = 0ull, a2 = 0ull, a3 = 0ull;                 \
            _Pragma("unroll")                                               \
            for (int k = 0; k < CC / 8; k++) {  /* 8 LDS.128, 32 ffma2 */   \
                ulonglong2 v0 = pv[2 * k];                                  \
                ulonglong2 v1 = pv[2 * k + 1];                              \
                a0 = ffma2(EC[4 * k],     v0.x, a0);                        \
                a1 = ffma2(EC[4 * k + 1], v0.y, a1);                        \
                a2 = ffma2(EC[4 * k + 2], v1.x, a2);                        \
                a3 = ffma2(EC[4 * k + 3], v1.y, a3);                        \
            }                                                               \
            float2 qq = upk2(fadd2(fadd2(a0, a1), fadd2(a2, a3)));          \
            float q = qq.x + qq.y;                                          \
            float e = CUR[s];                                               \
            float pn = m ? (q * __expf(e)) : cur;                           \
            if (m && j == tg) gold += e + trans[prev * CC + tg];            \
            if (m) prev = tg;                                               \
            if (s == 7) { /* renorm every 8 steps (2-warp reduce) */        \
                float sm = pn;                                              \
                _Pragma("unroll")                                           \
                for (int o = 16; o > 0; o >>= 1)                            \
                    sm += __shfl_xor_sync(0xffffffffu, sm, o);              \
                if (lane == 0) red[w] = sm;                                 \
                __syncthreads();                                            \
                float st = red[0] + red[1];                                 \
                M += __logf(st);                                            \
                pn *= (1.0f / st);                                          \
            }                                                               \
            p[(s + 1) & 1][j] = pn;                                         \
            __syncthreads();                                                \
            cur = pn;                                                       \
        }                                                                   \
    }

    for (int it2 = 0; it2 < TT / 16; it2++) {
        STEP8(ebufA, ebufB, it2 * 16)
        STEP8(ebufB, ebufA, it2 * 16 + 8)
    }
#undef STEP8

    // log_Z = M + log( sum_j p[j] * exp(trans[j][STOP]) )
    // (cur holds final p; t=511 hit the renorm so it is normalized)
    float v = cur * __expf(trans[j * CC + TAG_STOP]);
#pragma unroll
    for (int o = 16; o > 0; o >>= 1)
        v += __shfl_xor_sync(0xffffffffu, v, o);
    // gold partial reduce within warp too
#pragma unroll
    for (int o = 16; o > 0; o >>= 1)
        gold += __shfl_xor_sync(0xffffffffu, gold, o);

    __shared__ float redV[2], redG[2];
    if (lane == 0) { redV[w] = v; redG[w] = gold; }
    __syncthreads();

    if (j == 0) {
        float logZ = M + __logf(redV[0] + redV[1]);
        float g = redG[0] + redG[1] + trans[prev * CC + TAG_STOP];
        gRes[b] = logZ - g;
    }
    __threadfence();

    // Last block to finish computes the deterministic mean (warp 0 only).
    __shared__ unsigned int tkt;
    if (j == 0) tkt = atomicInc(&gTicket, BB - 1);   // wraps to 0 after BB
    __syncthreads();
    if (tkt == BB - 1 && w == 0) {
        __threadfence();
        float a = 0.0f;
        for (int k = lane; k < BB; k += 32)
            a += *((volatile float*)&gRes[k]);       // fixed order -> deterministic
#pragma unroll
        for (int o = 16; o > 0; o >>= 1)
            a += __shfl_xor_sync(0xffffffffu, a, o);
        if (lane == 0) out[0] = a * (1.0f / BB);
    }
}

// ---------------------------------------------------------------------------
extern "C" void kernel_launch(void* const* d_in, const int* in_sizes, int n_in,
                              void* d_out, int out_size) {
    const float* emissions = (const float*)d_in[0];
    const float* trans     = (const float*)d_in[1];
    const int*   tags      = (const int*)d_in[2];   // int32 (JAX x64 off)
    const int*   mask      = (const int*)d_in[3];
    float* out = (float*)d_out;

    crf_fused_kernel<<<BB, 64>>>(emissions, trans, tags, mask, out);
}